// round 11
// baseline (speedup 1.0000x reference)
#include <cuda_runtime.h>
#include <cstdint>

#define HG_L 16
#define HG_T (1u << 19)
#define HG_TMASK (HG_T - 1u)
#define WIDTH 64

#define P1 2654435761u
#define P2 805459861u
#define P3 3674653429u

typedef unsigned long long u64;

// Feature scratch: 48 level-slices x 2^20 points, one packed f32x2 each.
#define NPAD_LOG2 20
__device__ u64 g_enc[48u << NPAD_LOG2];   // 402 MB static scratch

// floor(16 * 1.5^l) for l = 0..15
__constant__ float c_res[HG_L] = {
    16.f, 24.f, 36.f, 54.f, 81.f, 121.f, 182.f, 273.f,
    410.f, 615.f, 922.f, 1383.f, 2075.f, 3113.f, 4670.f, 7006.f
};

// ---------- packed f32x2 helpers (Blackwell FFMA2) ----------
__device__ __forceinline__ u64 ffma2(u64 a, u64 b, u64 c) {
    u64 d;
    asm("fma.rn.f32x2 %0, %1, %2, %3;" : "=l"(d) : "l"(a), "l"(b), "l"(c));
    return d;
}
__device__ __forceinline__ u64 dup2(float x) {
    u64 d;
    asm("mov.b64 %0, {%1, %1};" : "=l"(d) : "f"(x));
    return d;
}
__device__ __forceinline__ u64 pack2(float lo, float hi) {
    u64 d;
    asm("mov.b64 %0, {%1, %2};" : "=l"(d) : "f"(lo), "f"(hi));
    return d;
}
__device__ __forceinline__ void unpack2(u64 x, float& lo, float& hi) {
    asm("mov.b64 {%0, %1}, %2;" : "=f"(lo), "=f"(hi) : "l"(x));
}

// ---------- gather primitives (R3 scheme, measured best) ----------
__device__ __forceinline__ void gather_pair(const float2* __restrict__ base,
                                            bool even, uint32_t ax0, uint32_t e,
                                            float vx0, float vx1, float wt,
                                            float& f0, float& f1) {
    if (even) {
        uint32_t id0 = (ax0 ^ e) & HG_TMASK;
        float4 q = __ldg((const float4*)base + (id0 >> 1));
        bool h = (id0 & 1u) != 0u;
        float wl = h ? vx1 : vx0;
        float wh = h ? vx0 : vx1;
        f0 = fmaf(wt, fmaf(wl, q.x, wh * q.z), f0);
        f1 = fmaf(wt, fmaf(wl, q.y, wh * q.w), f1);
    } else {
        float2 u = __ldg(base + ((ax0 ^ e) & HG_TMASK));
        float2 v = __ldg(base + (((ax0 + 1u) ^ e) & HG_TMASK));
        f0 = fmaf(wt, fmaf(vx0, u.x, vx1 * v.x), f0);
        f1 = fmaf(wt, fmaf(vx0, u.y, vx1 * v.y), f1);
    }
}

__device__ __forceinline__ void level3(float x0, float x1, float x2, float r,
                                       const float2* __restrict__ base,
                                       float& f0, float& f1) {
    float px = x0 * r, py = x1 * r, pz = x2 * r;
    float fx = floorf(px), fy = floorf(py), fz = floorf(pz);
    float wx = px - fx, wy = py - fy, wz = pz - fz;

    uint32_t ax0 = (uint32_t)fx;
    uint32_t ey0 = (uint32_t)fy * P1, ey1 = ey0 + P1;
    uint32_t ez0 = (uint32_t)fz * P2, ez1 = ez0 + P2;
    float vx0 = 1.f - wx, vx1 = wx;
    float vy0 = 1.f - wy, vy1 = wy;
    float vz0 = 1.f - wz, vz1 = wz;
    const bool even = (ax0 & 1u) == 0u;

    f0 = 0.f; f1 = 0.f;
    gather_pair(base, even, ax0, ey0 ^ ez0, vx0, vx1, vy0 * vz0, f0, f1);
    gather_pair(base, even, ax0, ey0 ^ ez1, vx0, vx1, vy0 * vz1, f0, f1);
    gather_pair(base, even, ax0, ey1 ^ ez0, vx0, vx1, vy1 * vz0, f0, f1);
    gather_pair(base, even, ax0, ey1 ^ ez1, vx0, vx1, vy1 * vz1, f0, f1);
}

__device__ __forceinline__ void level4(float x0, float x1, float x2, float x3,
                                       float r, const float2* __restrict__ base,
                                       float& f0, float& f1) {
    float px = x0 * r, py = x1 * r, pz = x2 * r, pw = x3 * r;
    float fx = floorf(px), fy = floorf(py), fz = floorf(pz), fw = floorf(pw);
    float wx = px - fx, wy = py - fy, wz = pz - fz, ww = pw - fw;

    uint32_t ax0 = (uint32_t)fx;
    uint32_t ey[2], ez[2], ew[2];
    ey[0] = (uint32_t)fy * P1;  ey[1] = ey[0] + P1;
    ez[0] = (uint32_t)fz * P2;  ez[1] = ez[0] + P2;
    ew[0] = (uint32_t)fw * P3;  ew[1] = ew[0] + P3;
    float vx0 = 1.f - wx, vx1 = wx;
    float vy[2] = {1.f - wy, wy};
    float vz[2] = {1.f - wz, wz};
    float vw[2] = {1.f - ww, ww};
    const bool even = (ax0 & 1u) == 0u;

    f0 = 0.f; f1 = 0.f;
#pragma unroll
    for (int c = 0; c < 8; c++) {
        const int by = (c >> 2) & 1, bz = (c >> 1) & 1, bw = c & 1;
        gather_pair(base, even, ax0, ey[by] ^ ez[bz] ^ ew[bw],
                    vx0, vx1, vy[by] * (vz[bz] * vw[bw]), f0, f1);
    }
}

// ---------- kernel 1: encode only (chunked) ----------
__global__ __launch_bounds__(256)
void encode_kernel(const float* __restrict__ fc,
                   const float* __restrict__ fn,
                   const float* __restrict__ pe,
                   const float* __restrict__ pos_tab,
                   const float* __restrict__ nrm_tab,
                   const float* __restrict__ pose_tab,
                   int off, int end) {
    const int idx = off + blockIdx.x * 256 + threadIdx.x;
    if (idx >= end) return;

    {
        float x0 = __ldg(fc + (size_t)idx * 3 + 0);
        float x1 = __ldg(fc + (size_t)idx * 3 + 1);
        float x2 = __ldg(fc + (size_t)idx * 3 + 2);
#pragma unroll 1
        for (int l = 0; l < HG_L; l++) {
            const float2* base = (const float2*)pos_tab + (size_t)l * HG_T;
            float f0, f1;
            level3(x0, x1, x2, c_res[l], base, f0, f1);
            g_enc[((size_t)l << NPAD_LOG2) + idx] = pack2(f0, f1);
        }
    }
    {
        float x0 = __ldg(fn + (size_t)idx * 3 + 0);
        float x1 = __ldg(fn + (size_t)idx * 3 + 1);
        float x2 = __ldg(fn + (size_t)idx * 3 + 2);
#pragma unroll 1
        for (int l = 0; l < HG_L; l++) {
            const float2* base = (const float2*)nrm_tab + (size_t)l * HG_T;
            float f0, f1;
            level3(x0, x1, x2, c_res[l], base, f0, f1);
            g_enc[((size_t)(16 + l) << NPAD_LOG2) + idx] = pack2(f0, f1);
        }
    }
    {
        float x0 = __ldg(pe + (size_t)idx * 4 + 0);
        float x1 = __ldg(pe + (size_t)idx * 4 + 1);
        float x2 = __ldg(pe + (size_t)idx * 4 + 2);
        float x3 = __ldg(pe + (size_t)idx * 4 + 3);
#pragma unroll 1
        for (int l = 0; l < HG_L; l++) {
            const float2* base = (const float2*)pose_tab + (size_t)l * HG_T;
            float f0, f1;
            level4(x0, x1, x2, x3, c_res[l], base, f0, f1);
            g_enc[((size_t)(32 + l) << NPAD_LOG2) + idx] = pack2(f0, f1);
        }
    }
}

// ---------- kernel 2: MLP (chunked), single point/thread ----------
__device__ __forceinline__ void acc_l1(const float* __restrict__ W1s, int row,
                                       float f0, float f1, u64* __restrict__ hp) {
    u64 F0 = dup2(f0), F1 = dup2(f1);
    const ulonglong2* w0 = (const ulonglong2*)(W1s + row * WIDTH);
    const ulonglong2* w1 = (const ulonglong2*)(W1s + (row + 1) * WIDTH);
#pragma unroll
    for (int j = 0; j < 16; j++) {
        ulonglong2 a = w0[j];
        ulonglong2 b = w1[j];
        hp[2 * j + 0] = ffma2(F0, a.x, ffma2(F1, b.x, hp[2 * j + 0]));
        hp[2 * j + 1] = ffma2(F0, a.y, ffma2(F1, b.y, hp[2 * j + 1]));
    }
}

__global__ __launch_bounds__(256, 2)
void mlp_kernel(const float* __restrict__ W1,
                const float* __restrict__ W2,
                const float* __restrict__ W3,
                float* __restrict__ out, int off, int end) {
    __shared__ float W1s[96 * WIDTH];       // 24 KB
    __shared__ float W2Ts[WIDTH * WIDTH];   // 16 KB (transposed)
    __shared__ float W3s[WIDTH * 9];        // 2.25 KB

    const int tid = threadIdx.x;
    for (int i = tid; i < 96 * WIDTH; i += 256) W1s[i] = W1[i];
    for (int i = tid; i < WIDTH * WIDTH; i += 256) {
        int k = i >> 6, j = i & 63;
        W2Ts[j * WIDTH + k] = W2[i];
    }
    for (int i = tid; i < WIDTH * 9; i += 256) W3s[i] = W3[i];
    __syncthreads();

    const int idx = off + blockIdx.x * 256 + tid;
    if (idx >= end) return;

    u64 hp[32];
#pragma unroll
    for (int j = 0; j < 32; j++) hp[j] = 0ull;

    // layer 1: features streamed from scratch (coalesced), weights LDS.128
#pragma unroll 1
    for (int l = 0; l < 48; l++) {
        u64 e = g_enc[((size_t)l << NPAD_LOG2) + idx];
        float f0, f1;
        unpack2(e, f0, f1);
        acc_l1(W1s, 2 * l, f0, f1, hp);
    }

    // relu(layer 1)
#pragma unroll
    for (int j = 0; j < 32; j++) {
        float lo, hi;
        unpack2(hp[j], lo, hi);
        hp[j] = pack2(fmaxf(lo, 0.f), fmaxf(hi, 0.f));
    }

    // layers 2 + 3: LDS.128 weight loads (ulonglong2), packed ffma2 dots
    float acc[9];
#pragma unroll
    for (int o = 0; o < 9; o++) acc[o] = 0.f;

#pragma unroll 1
    for (int j = 0; j < WIDTH; j++) {
        const ulonglong2* wr = (const ulonglong2*)(W2Ts + j * WIDTH);  // 16 x 16B
        u64 s0 = 0ull, s1 = 0ull;
#pragma unroll
        for (int k = 0; k < 16; k++) {
            ulonglong2 w = wr[k];
            s0 = ffma2(hp[2 * k + 0], w.x, s0);
            s1 = ffma2(hp[2 * k + 1], w.y, s1);
        }
        float a0, a1, a2, a3;
        unpack2(s0, a0, a1);
        unpack2(s1, a2, a3);
        float s = fmaxf((a0 + a1) + (a2 + a3), 0.f);
        const float* w3 = W3s + j * 9;
#pragma unroll
        for (int o = 0; o < 9; o++) acc[o] = fmaf(s, w3[o], acc[o]);
    }

    float* op = out + (size_t)idx * 9;
#pragma unroll
    for (int o = 0; o < 9; o++) op[o] = acc[o];
}

extern "C" void kernel_launch(void* const* d_in, const int* in_sizes, int n_in,
                              void* d_out, int out_size) {
    const float* fc = (const float*)d_in[0];
    const float* fn = (const float*)d_in[1];
    const float* pe = (const float*)d_in[2];
    const float* pt = (const float*)d_in[3];
    const float* nt = (const float*)d_in[4];
    const float* qt = (const float*)d_in[5];
    const float* W1 = (const float*)d_in[6];
    const float* W2 = (const float*)d_in[7];
    const float* W3 = (const float*)d_in[8];
    float* out = (float*)d_out;

    const int n = in_sizes[0] / 3;

    // Chunked pipeline: encode(c) on the launch stream, mlp(c) on a side
    // stream gated by an event -> mlp(c) overlaps encode(c+1). kernel_launch
    // runs only for correctness + capture (replays re-run the graph), so the
    // small number of stream/event objects created here is bounded.
    const int CH = 6;
    const int chunk = (n + CH - 1) / CH;

    cudaStream_t s2;
    cudaStreamCreateWithFlags(&s2, cudaStreamNonBlocking);

    for (int c = 0; c < CH; c++) {
        const int off = c * chunk;
        if (off >= n) break;
        const int end = (off + chunk < n) ? (off + chunk) : n;
        const int cnt = end - off;
        const int blocks = (cnt + 255) / 256;

        encode_kernel<<<blocks, 256, 0, 0>>>(fc, fn, pe, pt, nt, qt, off, end);

        cudaEvent_t ev;
        cudaEventCreateWithFlags(&ev, cudaEventDisableTiming);
        cudaEventRecord(ev, 0);
        cudaStreamWaitEvent(s2, ev, 0);

        mlp_kernel<<<blocks, 256, 0, s2>>>(W1, W2, W3, out, off, end);
    }

    // join: launch stream waits for the last mlp chunk
    cudaEvent_t done;
    cudaEventCreateWithFlags(&done, cudaEventDisableTiming);
    cudaEventRecord(done, s2);
    cudaStreamWaitEvent(0, done, 0);
}

// round 12
// speedup vs baseline: 1.0940x; 1.0940x over previous
#include <cuda_runtime.h>
#include <cstdint>

#define HG_L 16
#define HG_T (1u << 19)
#define HG_TMASK (HG_T - 1u)
#define WIDTH 64

#define P1 2654435761u
#define P2 805459861u
#define P3 3674653429u

typedef unsigned long long u64;

// Feature scratch: 48 level-slices x 2^20 points, one packed f32x2 each.
#define NPAD_LOG2 20
__device__ u64 g_enc[48u << NPAD_LOG2];   // 402 MB static scratch

// floor(16 * 1.5^l) for l = 0..15
__constant__ float c_res[HG_L] = {
    16.f, 24.f, 36.f, 54.f, 81.f, 121.f, 182.f, 273.f,
    410.f, 615.f, 922.f, 1383.f, 2075.f, 3113.f, 4670.f, 7006.f
};

// ---------- packed f32x2 helpers (Blackwell FFMA2) ----------
__device__ __forceinline__ u64 ffma2(u64 a, u64 b, u64 c) {
    u64 d;
    asm("fma.rn.f32x2 %0, %1, %2, %3;" : "=l"(d) : "l"(a), "l"(b), "l"(c));
    return d;
}
__device__ __forceinline__ u64 dup2(float x) {
    u64 d;
    asm("mov.b64 %0, {%1, %1};" : "=l"(d) : "f"(x));
    return d;
}
__device__ __forceinline__ u64 pack2(float lo, float hi) {
    u64 d;
    asm("mov.b64 %0, {%1, %2};" : "=l"(d) : "f"(lo), "f"(hi));
    return d;
}
__device__ __forceinline__ void unpack2(u64 x, float& lo, float& hi) {
    asm("mov.b64 {%0, %1}, %2;" : "=f"(lo), "=f"(hi) : "l"(x));
}

// ---------- gather primitive (R3 scheme, measured best) ----------
__device__ __forceinline__ void gather_pair(const float2* __restrict__ base,
                                            bool even, uint32_t ax0, uint32_t e,
                                            float vx0, float vx1, float wt,
                                            float& f0, float& f1) {
    if (even) {
        uint32_t id0 = (ax0 ^ e) & HG_TMASK;
        float4 q = __ldg((const float4*)base + (id0 >> 1));
        bool h = (id0 & 1u) != 0u;
        float wl = h ? vx1 : vx0;
        float wh = h ? vx0 : vx1;
        f0 = fmaf(wt, fmaf(wl, q.x, wh * q.z), f0);
        f1 = fmaf(wt, fmaf(wl, q.y, wh * q.w), f1);
    } else {
        float2 u = __ldg(base + ((ax0 ^ e) & HG_TMASK));
        float2 v = __ldg(base + (((ax0 + 1u) ^ e) & HG_TMASK));
        f0 = fmaf(wt, fmaf(vx0, u.x, vx1 * v.x), f0);
        f1 = fmaf(wt, fmaf(vx0, u.y, vx1 * v.y), f1);
    }
}

// Per-level 3D hash setup state.
struct Setup3 {
    uint32_t ax0, ey0, ey1, ez0, ez1;
    float vx0, vx1, vy0, vy1, vz0, vz1;
    bool even;
};
__device__ __forceinline__ Setup3 setup3(float x0, float x1, float x2, float r) {
    Setup3 s;
    float px = x0 * r, py = x1 * r, pz = x2 * r;
    float fx = floorf(px), fy = floorf(py), fz = floorf(pz);
    float wx = px - fx, wy = py - fy, wz = pz - fz;
    s.ax0 = (uint32_t)fx;
    s.ey0 = (uint32_t)fy * P1;  s.ey1 = s.ey0 + P1;
    s.ez0 = (uint32_t)fz * P2;  s.ez1 = s.ez0 + P2;
    s.vx0 = 1.f - wx;  s.vx1 = wx;
    s.vy0 = 1.f - wy;  s.vy1 = wy;
    s.vz0 = 1.f - wz;  s.vz1 = wz;
    s.even = (s.ax0 & 1u) == 0u;
    return s;
}

// ---------- kernel 1: encode only; two levels in flight per iteration ------
__global__ __launch_bounds__(256)
void encode_kernel(const float* __restrict__ fc,
                   const float* __restrict__ fn,
                   const float* __restrict__ pe,
                   const float* __restrict__ pos_tab,
                   const float* __restrict__ nrm_tab,
                   const float* __restrict__ pose_tab,
                   int n) {
    const int idx = blockIdx.x * 256 + threadIdx.x;
    if (idx >= n) return;

    // --- two 3D encodes, 2 levels per iteration (alternating gather issue) ---
    {
        float pX[3] = { __ldg(fc + (size_t)idx * 3 + 0),
                        __ldg(fc + (size_t)idx * 3 + 1),
                        __ldg(fc + (size_t)idx * 3 + 2) };
        float nX[3] = { __ldg(fn + (size_t)idx * 3 + 0),
                        __ldg(fn + (size_t)idx * 3 + 1),
                        __ldg(fn + (size_t)idx * 3 + 2) };
        const float* tabs[2] = { pos_tab, nrm_tab };
        const float* xs[2] = { pX, nX };
#pragma unroll 1
        for (int t = 0; t < 2; t++) {
            const float* tab = tabs[t];
            const float* X = xs[t];
            const int slice = t * 16;
#pragma unroll 1
            for (int l = 0; l < HG_L; l += 2) {
                Setup3 A = setup3(X[0], X[1], X[2], c_res[l]);
                Setup3 B = setup3(X[0], X[1], X[2], c_res[l + 1]);
                const float2* bA = (const float2*)tab + (size_t)l * HG_T;
                const float2* bB = (const float2*)tab + (size_t)(l + 1) * HG_T;

                float a0 = 0.f, a1 = 0.f, b0 = 0.f, b1 = 0.f;
                gather_pair(bA, A.even, A.ax0, A.ey0 ^ A.ez0, A.vx0, A.vx1, A.vy0 * A.vz0, a0, a1);
                gather_pair(bB, B.even, B.ax0, B.ey0 ^ B.ez0, B.vx0, B.vx1, B.vy0 * B.vz0, b0, b1);
                gather_pair(bA, A.even, A.ax0, A.ey0 ^ A.ez1, A.vx0, A.vx1, A.vy0 * A.vz1, a0, a1);
                gather_pair(bB, B.even, B.ax0, B.ey0 ^ B.ez1, B.vx0, B.vx1, B.vy0 * B.vz1, b0, b1);
                gather_pair(bA, A.even, A.ax0, A.ey1 ^ A.ez0, A.vx0, A.vx1, A.vy1 * A.vz0, a0, a1);
                gather_pair(bB, B.even, B.ax0, B.ey1 ^ B.ez0, B.vx0, B.vx1, B.vy1 * B.vz0, b0, b1);
                gather_pair(bA, A.even, A.ax0, A.ey1 ^ A.ez1, A.vx0, A.vx1, A.vy1 * A.vz1, a0, a1);
                gather_pair(bB, B.even, B.ax0, B.ey1 ^ B.ez1, B.vx0, B.vx1, B.vy1 * B.vz1, b0, b1);

                g_enc[((size_t)(slice + l) << NPAD_LOG2) + idx] = pack2(a0, a1);
                g_enc[((size_t)(slice + l + 1) << NPAD_LOG2) + idx] = pack2(b0, b1);
            }
        }
    }

    // --- 4D encode, 2 levels per iteration ---
    {
        float x0 = __ldg(pe + (size_t)idx * 4 + 0);
        float x1 = __ldg(pe + (size_t)idx * 4 + 1);
        float x2 = __ldg(pe + (size_t)idx * 4 + 2);
        float x3 = __ldg(pe + (size_t)idx * 4 + 3);
#pragma unroll 1
        for (int l = 0; l < HG_L; l += 2) {
            float fA0 = 0.f, fA1 = 0.f, fB0 = 0.f, fB1 = 0.f;

            // level A setup
            float rA = c_res[l], rB = c_res[l + 1];
            float pxA = x0 * rA, pyA = x1 * rA, pzA = x2 * rA, pwA = x3 * rA;
            float fxA = floorf(pxA), fyA = floorf(pyA), fzA = floorf(pzA), fwA = floorf(pwA);
            float wxA = pxA - fxA, wyA = pyA - fyA, wzA = pzA - fzA, wwA = pwA - fwA;
            uint32_t axA = (uint32_t)fxA;
            uint32_t eyA[2], ezA[2], ewA[2];
            eyA[0] = (uint32_t)fyA * P1;  eyA[1] = eyA[0] + P1;
            ezA[0] = (uint32_t)fzA * P2;  ezA[1] = ezA[0] + P2;
            ewA[0] = (uint32_t)fwA * P3;  ewA[1] = ewA[0] + P3;
            float vxA0 = 1.f - wxA, vxA1 = wxA;
            float vyA[2] = {1.f - wyA, wyA};
            float vzA[2] = {1.f - wzA, wzA};
            float vwA[2] = {1.f - wwA, wwA};
            bool evenA = (axA & 1u) == 0u;
            const float2* bA = (const float2*)pose_tab + (size_t)l * HG_T;

            // level B setup
            float pxB = x0 * rB, pyB = x1 * rB, pzB = x2 * rB, pwB = x3 * rB;
            float fxB = floorf(pxB), fyB = floorf(pyB), fzB = floorf(pzB), fwB = floorf(pwB);
            float wxB = pxB - fxB, wyB = pyB - fyB, wzB = pzB - fzB, wwB = pwB - fwB;
            uint32_t axB = (uint32_t)fxB;
            uint32_t eyB[2], ezB[2], ewB[2];
            eyB[0] = (uint32_t)fyB * P1;  eyB[1] = eyB[0] + P1;
            ezB[0] = (uint32_t)fzB * P2;  ezB[1] = ezB[0] + P2;
            ewB[0] = (uint32_t)fwB * P3;  ewB[1] = ewB[0] + P3;
            float vxB0 = 1.f - wxB, vxB1 = wxB;
            float vyB[2] = {1.f - wyB, wyB};
            float vzB[2] = {1.f - wzB, wzB};
            float vwB[2] = {1.f - wwB, wwB};
            bool evenB = (axB & 1u) == 0u;
            const float2* bB = (const float2*)pose_tab + (size_t)(l + 1) * HG_T;

#pragma unroll
            for (int c = 0; c < 8; c++) {
                const int by = (c >> 2) & 1, bz = (c >> 1) & 1, bw = c & 1;
                gather_pair(bA, evenA, axA, eyA[by] ^ ezA[bz] ^ ewA[bw],
                            vxA0, vxA1, vyA[by] * (vzA[bz] * vwA[bw]), fA0, fA1);
                gather_pair(bB, evenB, axB, eyB[by] ^ ezB[bz] ^ ewB[bw],
                            vxB0, vxB1, vyB[by] * (vzB[bz] * vwB[bw]), fB0, fB1);
            }

            g_enc[((size_t)(32 + l) << NPAD_LOG2) + idx] = pack2(fA0, fA1);
            g_enc[((size_t)(32 + l + 1) << NPAD_LOG2) + idx] = pack2(fB0, fB1);
        }
    }
}

// ---------- kernel 2: MLP, single point/thread, 2 CTAs/SM ----------
__device__ __forceinline__ void acc_l1(const float* __restrict__ W1s, int row,
                                       float f0, float f1, u64* __restrict__ hp) {
    u64 F0 = dup2(f0), F1 = dup2(f1);
    const ulonglong2* w0 = (const ulonglong2*)(W1s + row * WIDTH);
    const ulonglong2* w1 = (const ulonglong2*)(W1s + (row + 1) * WIDTH);
#pragma unroll
    for (int j = 0; j < 16; j++) {
        ulonglong2 a = w0[j];
        ulonglong2 b = w1[j];
        hp[2 * j + 0] = ffma2(F0, a.x, ffma2(F1, b.x, hp[2 * j + 0]));
        hp[2 * j + 1] = ffma2(F0, a.y, ffma2(F1, b.y, hp[2 * j + 1]));
    }
}

__global__ __launch_bounds__(256, 2)
void mlp_kernel(const float* __restrict__ W1,
                const float* __restrict__ W2,
                const float* __restrict__ W3,
                float* __restrict__ out, int n) {
    __shared__ float W1s[96 * WIDTH];       // 24 KB
    __shared__ float W2Ts[WIDTH * WIDTH];   // 16 KB (transposed)
    __shared__ float W3s[WIDTH * 9];        // 2.25 KB

    const int tid = threadIdx.x;
    for (int i = tid; i < 96 * WIDTH; i += 256) W1s[i] = W1[i];
    for (int i = tid; i < WIDTH * WIDTH; i += 256) {
        int k = i >> 6, j = i & 63;
        W2Ts[j * WIDTH + k] = W2[i];
    }
    for (int i = tid; i < WIDTH * 9; i += 256) W3s[i] = W3[i];
    __syncthreads();

    const int idx = blockIdx.x * 256 + tid;
    if (idx >= n) return;

    u64 hp[32];
#pragma unroll
    for (int j = 0; j < 32; j++) hp[j] = 0ull;

    // layer 1: features streamed from scratch (coalesced), weights LDS.128
#pragma unroll 1
    for (int l = 0; l < 48; l++) {
        u64 e = g_enc[((size_t)l << NPAD_LOG2) + idx];
        float f0, f1;
        unpack2(e, f0, f1);
        acc_l1(W1s, 2 * l, f0, f1, hp);
    }

    // relu(layer 1)
#pragma unroll
    for (int j = 0; j < 32; j++) {
        float lo, hi;
        unpack2(hp[j], lo, hi);
        hp[j] = pack2(fmaxf(lo, 0.f), fmaxf(hi, 0.f));
    }

    // layers 2 + 3: LDS.128 weight loads, packed ffma2 dots
    float acc[9];
#pragma unroll
    for (int o = 0; o < 9; o++) acc[o] = 0.f;

#pragma unroll 1
    for (int j = 0; j < WIDTH; j++) {
        const ulonglong2* wr = (const ulonglong2*)(W2Ts + j * WIDTH);  // 16 x 16B
        u64 s0 = 0ull, s1 = 0ull;
#pragma unroll
        for (int k = 0; k < 16; k++) {
            ulonglong2 w = wr[k];
            s0 = ffma2(hp[2 * k + 0], w.x, s0);
            s1 = ffma2(hp[2 * k + 1], w.y, s1);
        }
        float a0, a1, a2, a3;
        unpack2(s0, a0, a1);
        unpack2(s1, a2, a3);
        float s = fmaxf((a0 + a1) + (a2 + a3), 0.f);
        const float* w3 = W3s + j * 9;
#pragma unroll
        for (int o = 0; o < 9; o++) acc[o] = fmaf(s, w3[o], acc[o]);
    }

    float* op = out + (size_t)idx * 9;
#pragma unroll
    for (int o = 0; o < 9; o++) op[o] = acc[o];
}

extern "C" void kernel_launch(void* const* d_in, const int* in_sizes, int n_in,
                              void* d_out, int out_size) {
    const float* fc = (const float*)d_in[0];
    const float* fn = (const float*)d_in[1];
    const float* pe = (const float*)d_in[2];
    const float* pt = (const float*)d_in[3];
    const float* nt = (const float*)d_in[4];
    const float* qt = (const float*)d_in[5];
    const float* W1 = (const float*)d_in[6];
    const float* W2 = (const float*)d_in[7];
    const float* W3 = (const float*)d_in[8];
    float* out = (float*)d_out;

    const int n = in_sizes[0] / 3;

    encode_kernel<<<(n + 255) / 256, 256>>>(fc, fn, pe, pt, nt, qt, n);
    mlp_kernel<<<(n + 255) / 256, 256>>>(W1, W2, W3, out, n);
}